// round 3
// baseline (speedup 1.0000x reference)
#include <cuda_runtime.h>
#include <cuda_bf16.h>
#include <math.h>
#include <stdint.h>

// ---------------------------------------------------------------------------
// ConformalMIL forward.  B=32, S=2048, D=512, H=16, HD=32, NCLS=2, K=19
// out = [logits (32*2) | attn (32*16*2*2048)]  fp32
// GEMMs via mma.sync tf32 (m16n8k8); 3xTF32 split on logits-critical GEMMs.
// ---------------------------------------------------------------------------

#define Bb 32
#define Ss 2048
#define Dd 512
#define Mm (Bb * Ss)          // 65536
#define Hh 16
#define HDd 32
#define NCLS 2
#define KS 19

// scratch (static device arrays; no cudaMalloc allowed)
__device__ float g_ksum[Dd * KS];
__device__ float g_pos[(size_t)Mm * Dd];             // conv output (fp32)
__device__ float g_xn[(size_t)Mm * Dd];              // y then xn in-place
__device__ float g_k[(size_t)Mm * Dd];               // k (fp32)
__device__ float g_v[(size_t)Mm * Dd];               // v (fp32)
__device__ float g_q[NCLS * Dd];
__device__ float g_o[Bb * NCLS * Dd];

// ---------------------------------------------------------------------------
// helpers
// ---------------------------------------------------------------------------
__device__ __forceinline__ uint32_t smem_u32(const void* p) {
    uint32_t a;
    asm("{ .reg .u64 t; cvta.to.shared.u64 t, %1; cvt.u32.u64 %0, t; }" : "=r"(a) : "l"(p));
    return a;
}
__device__ __forceinline__ float to_tf32(float f) {
    uint32_t u;
    asm("cvt.rna.tf32.f32 %0, %1;" : "=r"(u) : "f"(f));
    return __uint_as_float(u);
}
__device__ __forceinline__ void mma8(float* d, const uint32_t* a, const uint32_t* b) {
    asm volatile("mma.sync.aligned.m16n8k8.row.col.f32.tf32.tf32.f32 "
        "{%0,%1,%2,%3}, {%4,%5,%6,%7}, {%8,%9}, {%0,%1,%2,%3};"
        : "+f"(d[0]), "+f"(d[1]), "+f"(d[2]), "+f"(d[3])
        : "r"(a[0]), "r"(a[1]), "r"(a[2]), "r"(a[3]), "r"(b[0]), "r"(b[1]));
}
#define LDS128(r, a) \
    asm volatile("ld.shared.v4.b32 {%0,%1,%2,%3}, [%4];" \
        : "=r"((r)[0]), "=r"((r)[1]), "=r"((r)[2]), "=r"((r)[3]) : "r"(a))
#define LDS64(r, a) \
    asm volatile("ld.shared.v2.b32 {%0,%1}, [%2];" \
        : "=r"((r)[0]), "=r"((r)[1]) : "r"(a))

// ---------------------------------------------------------------------------
// 1. wavelet kernels: ksum[d][t] = sum over 3 waves of mexican hat
// ---------------------------------------------------------------------------
__global__ void k_wavelet(const float* __restrict__ w1, const float* __restrict__ w2,
                          const float* __restrict__ w3) {
    int d = blockIdx.x * blockDim.x + threadIdx.x;
    if (d >= Dd) return;
    const float C = 2.0f / (sqrtf(3.0f) * powf(3.14159265358979323846f, 0.25f));
    const float* ws[3] = {w1, w2, w3};
    float sc[3], sh[3], rs[3];
    #pragma unroll
    for (int w = 0; w < 3; w++) {
        sc[w] = ws[w][d];
        sh[w] = ws[w][Dd + d];
        rs[w] = rsqrtf(fabsf(sc[w]));
    }
    for (int t = 0; t < KS; t++) {
        float xt = (float)(t - 9);
        float acc = 0.f;
        #pragma unroll
        for (int w = 0; w < 3; w++) {
            float u = (xt - sh[w]) / sc[w];
            acc += C * (1.f - u * u) * expf(-0.5f * u * u) * rs[w];
        }
        g_ksum[d * KS + t] = acc;
    }
}

// ---------------------------------------------------------------------------
// 2. depthwise conv along S ('SAME')
// ---------------------------------------------------------------------------
__global__ void k_dwconv(const float* __restrict__ x) {
    const int b  = blockIdx.z;
    const int s0 = blockIdx.y * 32;
    const int d0 = blockIdx.x * 128;
    __shared__ float xs[50][128];
    __shared__ float ks[KS][128];
    const int tid = threadIdx.x;  // 256

    for (int i = tid; i < KS * 128; i += 256) {
        int t = i >> 7, d = i & 127;
        ks[t][d] = g_ksum[(d0 + d) * KS + t];
    }
    const float* xb = x + (size_t)b * Ss * Dd;
    for (int i = tid; i < 50 * 32; i += 256) {
        int r = i >> 5, c4 = (i & 31) * 4;
        int s = s0 - 9 + r;
        float4 v = make_float4(0.f, 0.f, 0.f, 0.f);
        if (s >= 0 && s < Ss) v = *(const float4*)(xb + (size_t)s * Dd + d0 + c4);
        *(float4*)&xs[r][c4] = v;
    }
    __syncthreads();

    const int d = tid & 127;
    const int sr0 = tid >> 7;
    #pragma unroll
    for (int j = 0; j < 16; j++) {
        int sr = sr0 + j * 2;
        float acc = 0.f;
        #pragma unroll
        for (int t = 0; t < KS; t++) acc = fmaf(xs[sr + t][d], ks[t][d], acc);
        g_pos[((size_t)b * Ss + s0 + sr) * Dd + d0 + d] = acc;
    }
}

// ---------------------------------------------------------------------------
// 3. tf32 tensor-core GEMM:  C[M=65536, 512] tile-by-tile
//    CTA tile 128x128x32, 8 warps (2x4), warp tile 64x32, mma m16n8k8.
//    SMEM holds tiles pre-arranged in fragment order:
//      A-frag(mt 0..7, kt 0..3): 128 words at ((mt*4+kt)*128 + lane*4 + reg)
//      B-frag(nt 0..15, kt 0..3): 64 words at 4096 + ((nt*4+kt)*64 + lane*2 + reg)
//    SPLIT=1: 3xTF32 (hi/lo) for near-fp32 accuracy.
//    ADDX=1: epilogue adds xres + bias (GEMM1 residual).
// ---------------------------------------------------------------------------
#define BUFW(S) ((S) ? 16384 : 8192)

template <int SPLIT, int ADDX>
__global__ void __launch_bounds__(256, 1) k_mma(
    const float* __restrict__ A, const float* __restrict__ Bsrc, int ldb,
    const float* __restrict__ xres, const float* __restrict__ bias,
    float* __restrict__ outF)
{
    extern __shared__ float sm[];
    const int tid = threadIdx.x, warp = tid >> 5, lane = tid & 31;
    const int m0 = blockIdx.y * 128, n0 = blockIdx.x * 128;
    const int wmt = (warp >> 2) * 4;   // first m-tile of this warp (of 8)
    const int wnt = (warp & 3) * 4;    // first n-tile of this warp (of 16)

    float d[4][4][4];
    #pragma unroll
    for (int i = 0; i < 4; i++)
        #pragma unroll
        for (int j = 0; j < 4; j++)
            #pragma unroll
            for (int r = 0; r < 4; r++) d[i][j][r] = 0.f;

    float4 pa[4], pb[4];

#define LOAD_TILE(KT0) do {                                                     \
    const float* Ag = A + (size_t)m0 * Dd + (KT0) * 32;                         \
    _Pragma("unroll")                                                           \
    for (int i = 0; i < 4; i++) {                                               \
        int idx = tid + i * 256; int r = idx >> 3, c4 = (idx & 7) << 2;         \
        pa[i] = *(const float4*)(Ag + (size_t)r * Dd + c4);                     \
    }                                                                           \
    const float* Bg = Bsrc + (size_t)((KT0) * 32) * ldb + n0;                   \
    _Pragma("unroll")                                                           \
    for (int i = 0; i < 4; i++) {                                               \
        int idx = tid + i * 256; int kr = idx >> 5, n4 = (idx & 31) << 2;       \
        pb[i] = *(const float4*)(Bg + (size_t)kr * ldb + n4);                   \
    }                                                                           \
} while (0)

#define STORE_TILE(BUF) do {                                                    \
    float* Sh = sm + (BUF) * BUFW(SPLIT);                                       \
    _Pragma("unroll")                                                           \
    for (int i = 0; i < 4; i++) {                                               \
        int idx = tid + i * 256; int r = idx >> 3, c4 = (idx & 7) << 2;         \
        const float* v = (const float*)&pa[i];                                  \
        _Pragma("unroll")                                                       \
        for (int j = 0; j < 4; j++) {                                           \
            int k = c4 + j;                                                     \
            int mt = r >> 4, m = r & 15, kt = k >> 3, kc = k & 7;               \
            int w = (((mt << 2) + kt) << 7) + (((m & 7) << 2) + (kc & 3)) * 4   \
                    + ((kc >= 4) ? 2 : 0) + ((m >= 8) ? 1 : 0);                 \
            float hi = to_tf32(v[j]);                                           \
            Sh[w] = hi;                                                         \
            if (SPLIT) Sh[8192 + w] = to_tf32(v[j] - hi);                       \
        }                                                                       \
    }                                                                           \
    _Pragma("unroll")                                                           \
    for (int i = 0; i < 4; i++) {                                               \
        int idx = tid + i * 256; int kr = idx >> 5, n4 = (idx & 31) << 2;       \
        const float* v = (const float*)&pb[i];                                  \
        _Pragma("unroll")                                                       \
        for (int j = 0; j < 4; j++) {                                           \
            int n = n4 + j;                                                     \
            int nt = n >> 3, nc = n & 7, kt = kr >> 3, kc = kr & 7;             \
            int w = 4096 + (((nt << 2) + kt) << 6) + (nc * 4 + (kc & 3)) * 2    \
                    + ((kc >= 4) ? 1 : 0);                                      \
            float hi = to_tf32(v[j]);                                           \
            Sh[w] = hi;                                                         \
            if (SPLIT) Sh[8192 + w] = to_tf32(v[j] - hi);                       \
        }                                                                       \
    }                                                                           \
} while (0)

#define COMPUTE(BUF) do {                                                       \
    uint32_t Sb = smem_u32(sm + (BUF) * BUFW(SPLIT));                           \
    _Pragma("unroll")                                                           \
    for (int kt = 0; kt < 4; kt++) {                                            \
        uint32_t ah[4][4], bh[4][2], al[4][4], bl[4][2];                        \
        _Pragma("unroll")                                                       \
        for (int mt = 0; mt < 4; mt++) {                                        \
            uint32_t ad = Sb + ((((wmt + mt) << 2) + kt) * 128 + lane * 4) * 4; \
            LDS128(ah[mt], ad);                                                 \
            if (SPLIT) LDS128(al[mt], ad + 32768);                              \
        }                                                                       \
        _Pragma("unroll")                                                       \
        for (int nt = 0; nt < 4; nt++) {                                        \
            uint32_t bd = Sb + (4096 + (((wnt + nt) << 2) + kt) * 64 + lane * 2) * 4; \
            LDS64(bh[nt], bd);                                                  \
            if (SPLIT) LDS64(bl[nt], bd + 32768);                               \
        }                                                                       \
        _Pragma("unroll")                                                       \
        for (int mt = 0; mt < 4; mt++)                                          \
            _Pragma("unroll")                                                   \
            for (int nt = 0; nt < 4; nt++) mma8(d[mt][nt], ah[mt], bh[nt]);     \
        if (SPLIT) {                                                            \
            _Pragma("unroll")                                                   \
            for (int mt = 0; mt < 4; mt++)                                      \
                _Pragma("unroll")                                               \
                for (int nt = 0; nt < 4; nt++) mma8(d[mt][nt], al[mt], bh[nt]); \
            _Pragma("unroll")                                                   \
            for (int mt = 0; mt < 4; mt++)                                      \
                _Pragma("unroll")                                               \
                for (int nt = 0; nt < 4; nt++) mma8(d[mt][nt], ah[mt], bl[nt]); \
        }                                                                       \
    }                                                                           \
} while (0)

    LOAD_TILE(0);
    STORE_TILE(0);
    __syncthreads();
    #pragma unroll 1
    for (int kt0 = 0; kt0 < 16; kt0++) {
        int buf = kt0 & 1;
        if (kt0 + 1 < 16) LOAD_TILE(kt0 + 1);
        COMPUTE(buf);
        if (kt0 + 1 < 16) STORE_TILE(buf ^ 1);
        __syncthreads();
    }

    // epilogue
    const int gid = lane >> 2, tig = lane & 3;
    #pragma unroll
    for (int mt = 0; mt < 4; mt++) {
        #pragma unroll
        for (int nt = 0; nt < 4; nt++) {
            int row = m0 + (wmt + mt) * 16 + gid;
            int col = n0 + (wnt + nt) * 8 + tig * 2;
            float* D = d[mt][nt];
            float2 v0 = make_float2(D[0], D[1]);
            float2 v1 = make_float2(D[2], D[3]);
            if (ADDX) {
                const float* xr0 = xres + (size_t)row * Dd + col;
                const float* xr1 = xr0 + 8 * Dd;
                v0.x += xr0[0] + bias[col];     v0.y += xr0[1] + bias[col + 1];
                v1.x += xr1[0] + bias[col];     v1.y += xr1[1] + bias[col + 1];
            }
            *(float2*)(outF + (size_t)row * Dd + col)       = v0;
            *(float2*)(outF + (size_t)(row + 8) * Dd + col) = v1;
        }
    }
#undef LOAD_TILE
#undef STORE_TILE
#undef COMPUTE
}

// ---------------------------------------------------------------------------
// 4. LayerNorm in-place on rows of 512
// ---------------------------------------------------------------------------
__global__ void k_layernorm(float* __restrict__ y,
                            const float* __restrict__ g, const float* __restrict__ b) {
    const int row = blockIdx.x;
    float* p = y + (size_t)row * Dd;
    const int tid = threadIdx.x;   // 256
    float2 v = ((float2*)p)[tid];
    float sum = v.x + v.y;
    float sq  = v.x * v.x + v.y * v.y;
    #pragma unroll
    for (int o = 16; o; o >>= 1) {
        sum += __shfl_xor_sync(~0u, sum, o);
        sq  += __shfl_xor_sync(~0u, sq, o);
    }
    __shared__ float rs[8], rq[8];
    __shared__ float s_m, s_r;
    if ((tid & 31) == 0) { rs[tid >> 5] = sum; rq[tid >> 5] = sq; }
    __syncthreads();
    if (tid == 0) {
        float s = 0.f, q = 0.f;
        #pragma unroll
        for (int i = 0; i < 8; i++) { s += rs[i]; q += rq[i]; }
        float m = s / Dd;
        float var = q / Dd - m * m;
        s_m = m; s_r = rsqrtf(var + 1e-5f);
    }
    __syncthreads();
    const float m = s_m, r = s_r;
    float2 gv = ((const float2*)g)[tid];
    float2 bv = ((const float2*)b)[tid];
    v.x = (v.x - m) * r * gv.x + bv.x;
    v.y = (v.y - m) * r * gv.y + bv.y;
    ((float2*)p)[tid] = v;
}

// ---------------------------------------------------------------------------
// 5. q = cls_token @ Wq  [2, 512]  (fp32 exact)
// ---------------------------------------------------------------------------
__global__ void k_q(const float* __restrict__ cls, const float* __restrict__ Wq) {
    int idx = blockIdx.x * blockDim.x + threadIdx.x;
    int n = idx >> 9, j = idx & 511;
    float acc = 0.f;
    #pragma unroll 4
    for (int d = 0; d < Dd; d++) acc = fmaf(cls[n * Dd + d], Wq[(size_t)d * Dd + j], acc);
    g_q[n * Dd + j] = acc;
}

// ---------------------------------------------------------------------------
// 6. attention: sigmoid scores -> attn (output) and o = attn @ v
// ---------------------------------------------------------------------------
__global__ void k_attn(float* __restrict__ out_attn) {
    const int b = blockIdx.x >> 4;
    const int h = blockIdx.x & 15;
    const int tid = threadIdx.x;        // 256
    const int warp = tid >> 5, lane = tid & 31;
    __shared__ float qs[2][32];
    if (tid < 64) qs[tid >> 5][tid & 31] = g_q[(tid >> 5) * Dd + h * HDd + (tid & 31)];
    __syncthreads();
    const float q0 = qs[0][lane], q1 = qs[1][lane];
    const float scale = 0.17677669529663687f;   // 1/sqrt(32)
    const float logS  = 7.6246189861593985f;    // log(2048)
    float o0 = 0.f, o1 = 0.f;
    const float* kb = g_k + (size_t)b * Ss * Dd + h * HDd;
    const float* vb = g_v + (size_t)b * Ss * Dd + h * HDd;
    float* a0p = out_attn + (((size_t)b * Hh + h) * NCLS + 0) * Ss;
    float* a1p = a0p + Ss;

    const int sEnd = warp * 256 + 256;
    for (int s = warp * 256; s < sEnd; s++) {
        float kx = kb[(size_t)s * Dd + lane];
        float vx = vb[(size_t)s * Dd + lane];
        float d0 = q0 * kx, d1 = q1 * kx;
        #pragma unroll
        for (int o = 16; o; o >>= 1) {
            d0 += __shfl_xor_sync(~0u, d0, o);
            d1 += __shfl_xor_sync(~0u, d1, o);
        }
        float a0 = 1.f / (1.f + expf(-(d0 * scale - logS)));
        float a1 = 1.f / (1.f + expf(-(d1 * scale - logS)));
        o0 = fmaf(a0, vx, o0);
        o1 = fmaf(a1, vx, o1);
        if (lane == 0) a0p[s] = a0;
        if (lane == 1) a1p[s] = a1;
    }
    __shared__ float osh[8][2][32];
    osh[warp][0][lane] = o0;
    osh[warp][1][lane] = o1;
    __syncthreads();
    if (tid < 64) {
        int n = tid >> 5, l = tid & 31;
        float acc = 0.f;
        #pragma unroll
        for (int w = 0; w < 8; w++) acc += osh[w][n][l];
        g_o[((size_t)b * NCLS + n) * Dd + h * HDd + l] = acc;
    }
}

// ---------------------------------------------------------------------------
// 7. head (fp32)
// ---------------------------------------------------------------------------
__global__ void k_head(const float* __restrict__ Wproj, const float* __restrict__ bproj,
                       const float* __restrict__ ln2g, const float* __restrict__ ln2b,
                       const float* __restrict__ Wc1, const float* __restrict__ bc1,
                       const float* __restrict__ Wc2, const float* __restrict__ bc2,
                       float* __restrict__ logits) {
    const int r = blockIdx.x;
    const int tid = threadIdx.x;  // 256
    __shared__ float orow[Dd];
    __shared__ float prow[Dd];
    __shared__ float rs[8], rq[8];
    __shared__ float s_m, s_r;
    orow[tid]       = g_o[r * Dd + tid];
    orow[tid + 256] = g_o[r * Dd + tid + 256];
    __syncthreads();

    float pv[2];
    #pragma unroll
    for (int l = 0; l < 2; l++) {
        int j = tid + l * 256;
        float acc = bproj[j];
        #pragma unroll 4
        for (int d = 0; d < Dd; d++) acc = fmaf(orow[d], Wproj[(size_t)d * Dd + j], acc);
        pv[l] = acc;
    }
    float sum = pv[0] + pv[1];
    float sq  = pv[0] * pv[0] + pv[1] * pv[1];
    #pragma unroll
    for (int o = 16; o; o >>= 1) {
        sum += __shfl_xor_sync(~0u, sum, o);
        sq  += __shfl_xor_sync(~0u, sq, o);
    }
    if ((tid & 31) == 0) { rs[tid >> 5] = sum; rq[tid >> 5] = sq; }
    __syncthreads();
    if (tid == 0) {
        float s = 0.f, q = 0.f;
        #pragma unroll
        for (int i = 0; i < 8; i++) { s += rs[i]; q += rq[i]; }
        float m = s / Dd;
        float v = q / Dd - m * m;
        s_m = m; s_r = rsqrtf(v + 1e-5f);
    }
    __syncthreads();
    #pragma unroll
    for (int l = 0; l < 2; l++) {
        int j = tid + l * 256;
        prow[j] = (pv[l] - s_m) * s_r * ln2g[j] + ln2b[j];
    }
    __syncthreads();

    float part = 0.f;
    #pragma unroll
    for (int l = 0; l < 2; l++) {
        int j = tid + l * 256;
        float acc = bc1[j];
        #pragma unroll 4
        for (int d = 0; d < Dd; d++) acc = fmaf(prow[d], Wc1[(size_t)d * Dd + j], acc);
        acc = fmaxf(acc, 0.f);
        part = fmaf(acc, Wc2[j], part);
    }
    #pragma unroll
    for (int o = 16; o; o >>= 1) part += __shfl_xor_sync(~0u, part, o);
    if ((tid & 31) == 0) rs[tid >> 5] = part;
    __syncthreads();
    if (tid == 0) {
        float s = 0.f;
        #pragma unroll
        for (int i = 0; i < 8; i++) s += rs[i];
        logits[r] = s + bc2[0];
    }
}

// ---------------------------------------------------------------------------
extern "C" void kernel_launch(void* const* d_in, const int* in_sizes, int n_in,
                              void* d_out, int out_size) {
    const float* x      = (const float*)d_in[0];
    const float* wave1  = (const float*)d_in[1];
    const float* wave2  = (const float*)d_in[2];
    const float* wave3  = (const float*)d_in[3];
    const float* Wp1    = (const float*)d_in[4];
    const float* bp1    = (const float*)d_in[5];
    const float* cls    = (const float*)d_in[6];
    const float* ln1g   = (const float*)d_in[7];
    const float* ln1b   = (const float*)d_in[8];
    const float* Wq     = (const float*)d_in[9];
    const float* Wkv    = (const float*)d_in[10];
    const float* Wproj  = (const float*)d_in[11];
    const float* bproj  = (const float*)d_in[12];
    const float* ln2g   = (const float*)d_in[13];
    const float* ln2b   = (const float*)d_in[14];
    const float* Wc1    = (const float*)d_in[15];
    const float* bc1    = (const float*)d_in[16];
    const float* Wc2    = (const float*)d_in[17];
    const float* bc2    = (const float*)d_in[18];

    float* out = (float*)d_out;           // [0,64) logits, [64, ...) attn
    float* out_attn = out + Bb * NCLS;

    float* pos;  cudaGetSymbolAddress((void**)&pos,  g_pos);
    float* xn;   cudaGetSymbolAddress((void**)&xn,   g_xn);
    float* kbuf; cudaGetSymbolAddress((void**)&kbuf, g_k);
    float* vbuf; cudaGetSymbolAddress((void**)&vbuf, g_v);

    const int SM_SPLIT = 2 * BUFW(1) * 4;    // 128 KB
    const int SM_SINGLE = 2 * BUFW(0) * 4;   // 64 KB
    cudaFuncSetAttribute(k_mma<1, 1>, cudaFuncAttributeMaxDynamicSharedMemorySize, SM_SPLIT);
    cudaFuncSetAttribute(k_mma<1, 0>, cudaFuncAttributeMaxDynamicSharedMemorySize, SM_SPLIT);
    cudaFuncSetAttribute(k_mma<0, 0>, cudaFuncAttributeMaxDynamicSharedMemorySize, SM_SINGLE);

    // wavelet + conv
    k_wavelet<<<1, 512>>>(wave1, wave2, wave3);
    k_dwconv<<<dim3(Dd / 128, Ss / 32, Bb), 256>>>(x);
    // q (independent)
    k_q<<<4, 256>>>(cls, Wq);
    // GEMM1 (3xTF32): y = pos @ Wp1 + x + bp1   -> g_xn
    k_mma<1, 1><<<dim3(4, Mm / 128), 256, SM_SPLIT>>>(pos, Wp1, Dd, x, bp1, xn);
    // LN in place: xn
    k_layernorm<<<Mm, 256>>>(xn, ln1g, ln1b);
    // k = xn @ Wkv[:, :512]  (single-pass tf32)
    k_mma<0, 0><<<dim3(4, Mm / 128), 256, SM_SINGLE>>>(xn, Wkv, 2 * Dd, nullptr, nullptr, kbuf);
    // v = xn @ Wkv[:, 512:]  (3xTF32)
    k_mma<1, 0><<<dim3(4, Mm / 128), 256, SM_SPLIT>>>(xn, Wkv + Dd, 2 * Dd, nullptr, nullptr, vbuf);
    // attention + head
    k_attn<<<Bb * Hh, 256>>>(out_attn);
    k_head<<<Bb * NCLS, 256>>>(Wproj, bproj, ln2g, ln2b, Wc1, bc1, Wc2, bc2, out);
}

// round 4
// speedup vs baseline: 3.4894x; 3.4894x over previous
#include <cuda_runtime.h>
#include <cuda_bf16.h>
#include <math.h>
#include <stdint.h>

// ---------------------------------------------------------------------------
// ConformalMIL forward.  B=32, S=2048, D=512, H=16, HD=32, NCLS=2, K=19
// out = [logits (32*2) | attn (32*16*2*2048)]  fp32
// Only big GEMM (pos@Wp1) on mma.sync tf32 3x-split; attention path collapsed:
//   scores = xn @ Ws   (Ws = Wk-head-projected q, 512x32, fp32)
//   z      = attn^T @ xn  (per batch, 32x512, fp32)
//   o      = z @ Wv-head-blocks (tiny, fp32)
// ---------------------------------------------------------------------------

#define Bb 32
#define Ss 2048
#define Dd 512
#define Mm (Bb * Ss)          // 65536
#define Hh 16
#define HDd 32
#define NCLS 2
#define KS 19

// scratch (static device arrays; no cudaMalloc allowed)
__device__ float g_ksum[Dd * KS];
__device__ float g_pos[(size_t)Mm * Dd];             // conv output (fp32)
__device__ float g_xn[(size_t)Mm * Dd];              // y then xn in-place
__device__ float g_q[NCLS * Dd];
__device__ float g_ws[Dd * 32];                      // [d][(h*2+n)], scale folded
__device__ float g_z[Bb * 32 * Dd];                  // [b][(h*2+n)][d]
__device__ float g_o[Bb * NCLS * Dd];

// ---------------------------------------------------------------------------
// helpers
// ---------------------------------------------------------------------------
__device__ __forceinline__ uint32_t smem_u32(const void* p) {
    uint32_t a;
    asm("{ .reg .u64 t; cvta.to.shared.u64 t, %1; cvt.u32.u64 %0, t; }" : "=r"(a) : "l"(p));
    return a;
}
__device__ __forceinline__ float to_tf32(float f) {
    uint32_t u;
    asm("cvt.rna.tf32.f32 %0, %1;" : "=r"(u) : "f"(f));
    return __uint_as_float(u);
}
__device__ __forceinline__ void mma8(float* d, const uint32_t* a, const uint32_t* b) {
    asm volatile("mma.sync.aligned.m16n8k8.row.col.f32.tf32.tf32.f32 "
        "{%0,%1,%2,%3}, {%4,%5,%6,%7}, {%8,%9}, {%0,%1,%2,%3};"
        : "+f"(d[0]), "+f"(d[1]), "+f"(d[2]), "+f"(d[3])
        : "r"(a[0]), "r"(a[1]), "r"(a[2]), "r"(a[3]), "r"(b[0]), "r"(b[1]));
}
#define LDS128(r, a) \
    asm volatile("ld.shared.v4.b32 {%0,%1,%2,%3}, [%4];" \
        : "=r"((r)[0]), "=r"((r)[1]), "=r"((r)[2]), "=r"((r)[3]) : "r"(a))
#define LDS64(r, a) \
    asm volatile("ld.shared.v2.b32 {%0,%1}, [%2];" \
        : "=r"((r)[0]), "=r"((r)[1]) : "r"(a))

// ---------------------------------------------------------------------------
// 1. wavelet kernels
// ---------------------------------------------------------------------------
__global__ void k_wavelet(const float* __restrict__ w1, const float* __restrict__ w2,
                          const float* __restrict__ w3) {
    int d = blockIdx.x * blockDim.x + threadIdx.x;
    if (d >= Dd) return;
    const float C = 2.0f / (sqrtf(3.0f) * powf(3.14159265358979323846f, 0.25f));
    const float* ws[3] = {w1, w2, w3};
    float sc[3], sh[3], rs[3];
    #pragma unroll
    for (int w = 0; w < 3; w++) {
        sc[w] = ws[w][d];
        sh[w] = ws[w][Dd + d];
        rs[w] = rsqrtf(fabsf(sc[w]));
    }
    for (int t = 0; t < KS; t++) {
        float xt = (float)(t - 9);
        float acc = 0.f;
        #pragma unroll
        for (int w = 0; w < 3; w++) {
            float u = (xt - sh[w]) / sc[w];
            acc += C * (1.f - u * u) * expf(-0.5f * u * u) * rs[w];
        }
        g_ksum[d * KS + t] = acc;
    }
}

// ---------------------------------------------------------------------------
// 2. depthwise conv along S ('SAME')
// ---------------------------------------------------------------------------
__global__ void k_dwconv(const float* __restrict__ x) {
    const int b  = blockIdx.z;
    const int s0 = blockIdx.y * 32;
    const int d0 = blockIdx.x * 128;
    __shared__ float xs[50][128];
    __shared__ float ks[KS][128];
    const int tid = threadIdx.x;  // 256

    for (int i = tid; i < KS * 128; i += 256) {
        int t = i >> 7, d = i & 127;
        ks[t][d] = g_ksum[(d0 + d) * KS + t];
    }
    const float* xb = x + (size_t)b * Ss * Dd;
    for (int i = tid; i < 50 * 32; i += 256) {
        int r = i >> 5, c4 = (i & 31) * 4;
        int s = s0 - 9 + r;
        float4 v = make_float4(0.f, 0.f, 0.f, 0.f);
        if (s >= 0 && s < Ss) v = *(const float4*)(xb + (size_t)s * Dd + d0 + c4);
        *(float4*)&xs[r][c4] = v;
    }
    __syncthreads();

    const int d = tid & 127;
    const int sr0 = tid >> 7;
    #pragma unroll
    for (int j = 0; j < 16; j++) {
        int sr = sr0 + j * 2;
        float acc = 0.f;
        #pragma unroll
        for (int t = 0; t < KS; t++) acc = fmaf(xs[sr + t][d], ks[t][d], acc);
        g_pos[((size_t)b * Ss + s0 + sr) * Dd + d0 + d] = acc;
    }
}

// ---------------------------------------------------------------------------
// 3. GEMM1 (3xTF32): y = pos @ Wp1 + x + bp1
//    CTA tile 128x128x32, 8 warps, warp 64x32, mma m16n8k8.
//    Fragment-order smem with XOR swizzles (A: ^kt<<2, B: ^nt<<1) so the
//    scatter stores are <=2-way conflicted and frag loads stay vectorized.
// ---------------------------------------------------------------------------
#define BUFW 16384

__global__ void __launch_bounds__(256, 1) k_mma(
    const float* __restrict__ A, const float* __restrict__ Bsrc,
    const float* __restrict__ xres, const float* __restrict__ bias,
    float* __restrict__ outF)
{
    extern __shared__ float sm[];
    const int tid = threadIdx.x, warp = tid >> 5, lane = tid & 31;
    const int m0 = blockIdx.y * 128, n0 = blockIdx.x * 128;
    const int wmt = (warp >> 2) * 4;
    const int wnt = (warp & 3) * 4;

    float d[4][4][4];
    #pragma unroll
    for (int i = 0; i < 4; i++)
        #pragma unroll
        for (int j = 0; j < 4; j++)
            #pragma unroll
            for (int r = 0; r < 4; r++) d[i][j][r] = 0.f;

    float4 pa[4], pb[4];

#define LOAD_TILE(KT0) do {                                                     \
    const float* Ag = A + (size_t)m0 * Dd + (KT0) * 32;                         \
    _Pragma("unroll")                                                           \
    for (int i = 0; i < 4; i++) {                                               \
        int idx = tid + i * 256; int r = idx >> 3, c4 = (idx & 7) << 2;         \
        pa[i] = *(const float4*)(Ag + (size_t)r * Dd + c4);                     \
    }                                                                           \
    const float* Bg = Bsrc + (size_t)((KT0) * 32) * Dd + n0;                    \
    _Pragma("unroll")                                                           \
    for (int i = 0; i < 4; i++) {                                               \
        int idx = tid + i * 256; int kr = idx >> 5, n4 = (idx & 31) << 2;       \
        pb[i] = *(const float4*)(Bg + (size_t)kr * Dd + n4);                    \
    }                                                                           \
} while (0)

#define STORE_TILE(BUF) do {                                                    \
    float* Sh = sm + (BUF) * BUFW;                                              \
    _Pragma("unroll")                                                           \
    for (int i = 0; i < 4; i++) {                                               \
        int idx = tid + i * 256; int r = idx >> 3, c4 = (idx & 7) << 2;         \
        const float* v = (const float*)&pa[i];                                  \
        _Pragma("unroll")                                                       \
        for (int j = 0; j < 4; j++) {                                           \
            int k = c4 + j;                                                     \
            int mt = r >> 4, m = r & 15, kt = k >> 3, kc = k & 7;               \
            int elem = (((m & 7) << 2) + (kc & 3)) * 4                          \
                       + ((kc >= 4) ? 2 : 0) + ((m >= 8) ? 1 : 0);              \
            elem ^= (kt << 2);                                                  \
            int w = (((mt << 2) + kt) << 7) + elem;                             \
            float hi = to_tf32(v[j]);                                           \
            Sh[w] = hi;                                                         \
            Sh[8192 + w] = to_tf32(v[j] - hi);                                  \
        }                                                                       \
    }                                                                           \
    _Pragma("unroll")                                                           \
    for (int i = 0; i < 4; i++) {                                               \
        int idx = tid + i * 256; int kr = idx >> 5, n4 = (idx & 31) << 2;       \
        const float* v = (const float*)&pb[i];                                  \
        _Pragma("unroll")                                                       \
        for (int j = 0; j < 4; j++) {                                           \
            int n = n4 + j;                                                     \
            int nt = n >> 3, nc = n & 7, kt = kr >> 3, kc = kr & 7;             \
            int elem = (nc * 4 + (kc & 3)) * 2 + ((kc >= 4) ? 1 : 0);           \
            elem ^= (nt << 1);                                                  \
            int w = 4096 + (((nt << 2) + kt) << 6) + elem;                      \
            float hi = to_tf32(v[j]);                                           \
            Sh[w] = hi;                                                         \
            Sh[8192 + w] = to_tf32(v[j] - hi);                                  \
        }                                                                       \
    }                                                                           \
} while (0)

#define COMPUTE(BUF) do {                                                       \
    uint32_t Sb = smem_u32(sm + (BUF) * BUFW);                                  \
    _Pragma("unroll")                                                           \
    for (int kt = 0; kt < 4; kt++) {                                            \
        uint32_t ah[4][4], bh[4][2], al[4][4], bl[4][2];                        \
        _Pragma("unroll")                                                       \
        for (int mt = 0; mt < 4; mt++) {                                        \
            uint32_t ad = Sb + (((((wmt + mt) << 2) + kt) << 7)                 \
                                + ((lane << 2) ^ (kt << 2))) * 4;               \
            LDS128(ah[mt], ad);                                                 \
            LDS128(al[mt], ad + 32768);                                         \
        }                                                                       \
        _Pragma("unroll")                                                       \
        for (int nt = 0; nt < 4; nt++) {                                        \
            int ntt = wnt + nt;                                                 \
            uint32_t bd = Sb + (4096 + (((ntt << 2) + kt) << 6)                 \
                                + ((lane << 1) ^ (ntt << 1))) * 4;              \
            LDS64(bh[nt], bd);                                                  \
            LDS64(bl[nt], bd + 32768);                                          \
        }                                                                       \
        _Pragma("unroll")                                                       \
        for (int mt = 0; mt < 4; mt++)                                          \
            _Pragma("unroll")                                                   \
            for (int nt = 0; nt < 4; nt++) mma8(d[mt][nt], ah[mt], bh[nt]);     \
        _Pragma("unroll")                                                       \
        for (int mt = 0; mt < 4; mt++)                                          \
            _Pragma("unroll")                                                   \
            for (int nt = 0; nt < 4; nt++) mma8(d[mt][nt], al[mt], bh[nt]);     \
        _Pragma("unroll")                                                       \
        for (int mt = 0; mt < 4; mt++)                                          \
            _Pragma("unroll")                                                   \
            for (int nt = 0; nt < 4; nt++) mma8(d[mt][nt], ah[mt], bl[nt]);     \
    }                                                                           \
} while (0)

    LOAD_TILE(0);
    STORE_TILE(0);
    __syncthreads();
    #pragma unroll 1
    for (int kt0 = 0; kt0 < 16; kt0++) {
        int buf = kt0 & 1;
        if (kt0 + 1 < 16) LOAD_TILE(kt0 + 1);
        COMPUTE(buf);
        if (kt0 + 1 < 16) STORE_TILE(buf ^ 1);
        __syncthreads();
    }

    // epilogue: + x + bias
    const int gid = lane >> 2, tig = lane & 3;
    #pragma unroll
    for (int mt = 0; mt < 4; mt++) {
        #pragma unroll
        for (int nt = 0; nt < 4; nt++) {
            int row = m0 + (wmt + mt) * 16 + gid;
            int col = n0 + (wnt + nt) * 8 + tig * 2;
            float* D = d[mt][nt];
            float2 v0 = make_float2(D[0], D[1]);
            float2 v1 = make_float2(D[2], D[3]);
            const float* xr0 = xres + (size_t)row * Dd + col;
            const float* xr1 = xr0 + 8 * Dd;
            v0.x += xr0[0] + bias[col];     v0.y += xr0[1] + bias[col + 1];
            v1.x += xr1[0] + bias[col];     v1.y += xr1[1] + bias[col + 1];
            *(float2*)(outF + (size_t)row * Dd + col)       = v0;
            *(float2*)(outF + (size_t)(row + 8) * Dd + col) = v1;
        }
    }
#undef LOAD_TILE
#undef STORE_TILE
#undef COMPUTE
}

// ---------------------------------------------------------------------------
// 4. LayerNorm in-place on rows of 512
// ---------------------------------------------------------------------------
__global__ void k_layernorm(float* __restrict__ y,
                            const float* __restrict__ g, const float* __restrict__ b) {
    const int row = blockIdx.x;
    float* p = y + (size_t)row * Dd;
    const int tid = threadIdx.x;   // 256
    float2 v = ((float2*)p)[tid];
    float sum = v.x + v.y;
    float sq  = v.x * v.x + v.y * v.y;
    #pragma unroll
    for (int o = 16; o; o >>= 1) {
        sum += __shfl_xor_sync(~0u, sum, o);
        sq  += __shfl_xor_sync(~0u, sq, o);
    }
    __shared__ float rs[8], rq[8];
    __shared__ float s_m, s_r;
    if ((tid & 31) == 0) { rs[tid >> 5] = sum; rq[tid >> 5] = sq; }
    __syncthreads();
    if (tid == 0) {
        float s = 0.f, q = 0.f;
        #pragma unroll
        for (int i = 0; i < 8; i++) { s += rs[i]; q += rq[i]; }
        float m = s / Dd;
        float var = q / Dd - m * m;
        s_m = m; s_r = rsqrtf(var + 1e-5f);
    }
    __syncthreads();
    const float m = s_m, r = s_r;
    float2 gv = ((const float2*)g)[tid];
    float2 bv = ((const float2*)b)[tid];
    v.x = (v.x - m) * r * gv.x + bv.x;
    v.y = (v.y - m) * r * gv.y + bv.y;
    ((float2*)p)[tid] = v;
}

// ---------------------------------------------------------------------------
// 5a. q = cls_token @ Wq  [2, 512]  (fp32 exact)
// ---------------------------------------------------------------------------
__global__ void k_q(const float* __restrict__ cls, const float* __restrict__ Wq) {
    int idx = blockIdx.x * blockDim.x + threadIdx.x;
    int n = idx >> 9, j = idx & 511;
    float acc = 0.f;
    #pragma unroll 4
    for (int d = 0; d < Dd; d++) acc = fmaf(cls[n * Dd + d], Wq[(size_t)d * Dd + j], acc);
    g_q[n * Dd + j] = acc;
}

// ---------------------------------------------------------------------------
// 5b. Ws[d][(h*2+n)] = scale * sum_hd Wkv[d][h*32+hd] * q[n][h*32+hd]
// ---------------------------------------------------------------------------
__global__ void k_ws(const float* __restrict__ Wkv) {
    int idx = blockIdx.x * blockDim.x + threadIdx.x;   // 16384
    int d = idx >> 5, c = idx & 31;
    int h = c >> 1, n = c & 1;
    const float scale = 0.17677669529663687f;   // 1/sqrt(32)
    float acc = 0.f;
    #pragma unroll
    for (int hd = 0; hd < HDd; hd++)
        acc = fmaf(Wkv[(size_t)d * (2 * Dd) + h * HDd + hd], g_q[n * Dd + h * HDd + hd], acc);
    g_ws[d * 32 + c] = acc * scale;
}

// ---------------------------------------------------------------------------
// 6. scores + sigmoid -> attn (direct to output, [b,h,n,s] layout)
//    sc[m, c] = xn[m,:] @ Ws[:,c];  attn = sigmoid(sc - log S)
//    block: 128 rows x 32 cols, 256 threads (4x4 per thread), K chunks of 32
// ---------------------------------------------------------------------------
__global__ void __launch_bounds__(256) k_scores(float* __restrict__ out_attn) {
    __shared__ float xs[128][33];
    __shared__ float wss[32][32];
    const int tid = threadIdx.x;
    const int m0 = blockIdx.x * 128;
    const int rb = (tid >> 3) * 4;       // row base (0..124)
    const int c0 = (tid & 7) * 4;        // col base (0..28)
    const float logS = 7.6246189861593985f;   // log(2048)

    float acc[4][4];
    #pragma unroll
    for (int i = 0; i < 4; i++)
        #pragma unroll
        for (int j = 0; j < 4; j++) acc[i][j] = 0.f;

    for (int k0 = 0; k0 < Dd; k0 += 32) {
        // load xn chunk [128][32]
        #pragma unroll
        for (int l = 0; l < 4; l++) {
            int idx = tid + l * 256;
            int r = idx >> 3, k4 = (idx & 7) * 4;
            float4 v = *(const float4*)(g_xn + (size_t)(m0 + r) * Dd + k0 + k4);
            xs[r][k4] = v.x; xs[r][k4 + 1] = v.y; xs[r][k4 + 2] = v.z; xs[r][k4 + 3] = v.w;
        }
        // load Ws chunk [32][32]
        {
            int kk = tid >> 3, c4 = (tid & 7) * 4;
            *(float4*)&wss[kk][c4] = *(const float4*)(g_ws + (size_t)(k0 + kk) * 32 + c4);
        }
        __syncthreads();
        #pragma unroll 4
        for (int kk = 0; kk < 32; kk++) {
            float w[4], a[4];
            #pragma unroll
            for (int j = 0; j < 4; j++) w[j] = wss[kk][c0 + j];
            #pragma unroll
            for (int i = 0; i < 4; i++) a[i] = xs[rb + i][kk];
            #pragma unroll
            for (int i = 0; i < 4; i++)
                #pragma unroll
                for (int j = 0; j < 4; j++) acc[i][j] = fmaf(a[i], w[j], acc[i][j]);
        }
        __syncthreads();
    }
    #pragma unroll
    for (int i = 0; i < 4; i++) {
        int m = m0 + rb + i;
        int b = m >> 11, s = m & 2047;
        #pragma unroll
        for (int j = 0; j < 4; j++) {
            float a = 1.f / (1.f + expf(logS - acc[i][j]));
            out_attn[(size_t)b * (Hh * NCLS * Ss) + (size_t)(c0 + j) * Ss + s] = a;
        }
    }
}

// ---------------------------------------------------------------------------
// 7. z[b][(h,n)][d] = sum_s attn[b,(h,n),s] * xn[b,s,d]
//    block: b = blockIdx.y, dtile = blockIdx.x*128; M=32, N=128, K=2048/64
// ---------------------------------------------------------------------------
__global__ void __launch_bounds__(256) k_z(const float* __restrict__ out_attn) {
    __shared__ float at[32][65];
    __shared__ float xs[64][128];
    const int tid = threadIdx.x;
    const int b = blockIdx.y;
    const int n0 = blockIdx.x * 128;
    const int rb = (tid >> 5) * 4;      // rows (h,n): 0..28
    const int cb = (tid & 31) * 4;      // cols d: 0..124

    float acc[4][4];
    #pragma unroll
    for (int i = 0; i < 4; i++)
        #pragma unroll
        for (int j = 0; j < 4; j++) acc[i][j] = 0.f;

    const float* ab = out_attn + (size_t)b * (Hh * NCLS * Ss);
    const float* xb = g_xn + (size_t)b * Ss * Dd;

    for (int s0 = 0; s0 < Ss; s0 += 64) {
        // attn tile [32][64]
        #pragma unroll
        for (int l = 0; l < 8; l++) {
            int idx = tid + l * 256;
            int hn = idx >> 6, so = idx & 63;
            at[hn][so] = ab[(size_t)hn * Ss + s0 + so];
        }
        // xn tile [64][128]
        #pragma unroll
        for (int l = 0; l < 8; l++) {
            int idx = tid + l * 256;
            int ss = idx >> 5, d4 = (idx & 31) * 4;
            *(float4*)&xs[ss][d4] = *(const float4*)(xb + (size_t)(s0 + ss) * Dd + n0 + d4);
        }
        __syncthreads();
        #pragma unroll 4
        for (int ss = 0; ss < 64; ss++) {
            float4 xv = *(float4*)&xs[ss][cb];
            float a[4];
            #pragma unroll
            for (int i = 0; i < 4; i++) a[i] = at[rb + i][ss];
            #pragma unroll
            for (int i = 0; i < 4; i++) {
                acc[i][0] = fmaf(a[i], xv.x, acc[i][0]);
                acc[i][1] = fmaf(a[i], xv.y, acc[i][1]);
                acc[i][2] = fmaf(a[i], xv.z, acc[i][2]);
                acc[i][3] = fmaf(a[i], xv.w, acc[i][3]);
            }
        }
        __syncthreads();
    }
    #pragma unroll
    for (int i = 0; i < 4; i++) {
        float4 v = make_float4(acc[i][0], acc[i][1], acc[i][2], acc[i][3]);
        *(float4*)(g_z + ((size_t)b * 32 + rb + i) * Dd + n0 + cb) = v;
    }
}

// ---------------------------------------------------------------------------
// 8. o[b][n][h*32+d'] = sum_d z[b][(h*2+n)][d] * Wkv[d][512 + h*32+d']
// ---------------------------------------------------------------------------
__global__ void __launch_bounds__(512) k_o(const float* __restrict__ Wkv) {
    __shared__ float zr[16][Dd];
    const int bn = blockIdx.x;           // b*2+n
    const int b = bn >> 1, n = bn & 1;
    const int j = threadIdx.x;           // 512
    // stage the 16 z rows (h, n) for this (b, n)
    for (int i = j; i < 16 * Dd; i += 512) {
        int h = i >> 9, d = i & 511;
        zr[h][d] = g_z[((size_t)b * 32 + h * 2 + n) * Dd + d];
    }
    __syncthreads();
    const int h = j >> 5;
    float acc = 0.f;
    #pragma unroll 4
    for (int d = 0; d < Dd; d++)
        acc = fmaf(zr[h][d], Wkv[(size_t)d * (2 * Dd) + Dd + j], acc);
    g_o[(size_t)bn * Dd + j] = acc;
}

// ---------------------------------------------------------------------------
// 9. head (fp32)
// ---------------------------------------------------------------------------
__global__ void k_head(const float* __restrict__ Wproj, const float* __restrict__ bproj,
                       const float* __restrict__ ln2g, const float* __restrict__ ln2b,
                       const float* __restrict__ Wc1, const float* __restrict__ bc1,
                       const float* __restrict__ Wc2, const float* __restrict__ bc2,
                       float* __restrict__ logits) {
    const int r = blockIdx.x;
    const int tid = threadIdx.x;  // 256
    __shared__ float orow[Dd];
    __shared__ float prow[Dd];
    __shared__ float rs[8], rq[8];
    __shared__ float s_m, s_r;
    orow[tid]       = g_o[r * Dd + tid];
    orow[tid + 256] = g_o[r * Dd + tid + 256];
    __syncthreads();

    float pv[2];
    #pragma unroll
    for (int l = 0; l < 2; l++) {
        int j = tid + l * 256;
        float acc = bproj[j];
        #pragma unroll 4
        for (int d = 0; d < Dd; d++) acc = fmaf(orow[d], Wproj[(size_t)d * Dd + j], acc);
        pv[l] = acc;
    }
    float sum = pv[0] + pv[1];
    float sq  = pv[0] * pv[0] + pv[1] * pv[1];
    #pragma unroll
    for (int o = 16; o; o >>= 1) {
        sum += __shfl_xor_sync(~0u, sum, o);
        sq  += __shfl_xor_sync(~0u, sq, o);
    }
    if ((tid & 31) == 0) { rs[tid >> 5] = sum; rq[tid >> 5] = sq; }
    __syncthreads();
    if (tid == 0) {
        float s = 0.f, q = 0.f;
        #pragma unroll
        for (int i = 0; i < 8; i++) { s += rs[i]; q += rq[i]; }
        float m = s / Dd;
        float v = q / Dd - m * m;
        s_m = m; s_r = rsqrtf(v + 1e-5f);
    }
    __syncthreads();
    #pragma unroll
    for (int l = 0; l < 2; l++) {
        int j = tid + l * 256;
        prow[j] = (pv[l] - s_m) * s_r * ln2g[j] + ln2b[j];
    }
    __syncthreads();

    float part = 0.f;
    #pragma unroll
    for (int l = 0; l < 2; l++) {
        int j = tid + l * 256;
        float acc = bc1[j];
        #pragma unroll 4
        for (int d = 0; d < Dd; d++) acc = fmaf(prow[d], Wc1[(size_t)d * Dd + j], acc);
        acc = fmaxf(acc, 0.f);
        part = fmaf(acc, Wc2[j], part);
    }
    #pragma unroll
    for (int o = 16; o; o >>= 1) part += __shfl_xor_sync(~0u, part, o);
    if ((tid & 31) == 0) rs[tid >> 5] = part;
    __syncthreads();
    if (tid == 0) {
        float s = 0.f;
        #pragma unroll
        for (int i = 0; i < 8; i++) s += rs[i];
        logits[r] = s + bc2[0];
    }
}

// ---------------------------------------------------------------------------
extern "C" void kernel_launch(void* const* d_in, const int* in_sizes, int n_in,
                              void* d_out, int out_size) {
    const float* x      = (const float*)d_in[0];
    const float* wave1  = (const float*)d_in[1];
    const float* wave2  = (const float*)d_in[2];
    const float* wave3  = (const float*)d_in[3];
    const float* Wp1    = (const float*)d_in[4];
    const float* bp1    = (const float*)d_in[5];
    const float* cls    = (const float*)d_in[6];
    const float* ln1g   = (const float*)d_in[7];
    const float* ln1b   = (const float*)d_in[8];
    const float* Wq     = (const float*)d_in[9];
    const float* Wkv    = (const float*)d_in[10];
    const float* Wproj  = (const float*)d_in[11];
    const float* bproj  = (const float*)d_in[12];
    const float* ln2g   = (const float*)d_in[13];
    const float* ln2b   = (const float*)d_in[14];
    const float* Wc1    = (const float*)d_in[15];
    const float* bc1    = (const float*)d_in[16];
    const float* Wc2    = (const float*)d_in[17];
    const float* bc2    = (const float*)d_in[18];

    float* out = (float*)d_out;           // [0,64) logits, [64, ...) attn
    float* out_attn = out + Bb * NCLS;

    float* pos;  cudaGetSymbolAddress((void**)&pos,  g_pos);
    float* xn;   cudaGetSymbolAddress((void**)&xn,   g_xn);

    const int SM_SPLIT = 2 * BUFW * 4;    // 128 KB
    cudaFuncSetAttribute(k_mma, cudaFuncAttributeMaxDynamicSharedMemorySize, SM_SPLIT);

    // wavelet + conv
    k_wavelet<<<1, 512>>>(wave1, wave2, wave3);
    k_dwconv<<<dim3(Dd / 128, Ss / 32, Bb), 256>>>(x);
    // q, Ws (independent of conv)
    k_q<<<4, 256>>>(cls, Wq);
    k_ws<<<64, 256>>>(Wkv);
    // GEMM1 (3xTF32): y = pos @ Wp1 + x + bp1 -> g_xn
    k_mma<<<dim3(4, Mm / 128), 256, SM_SPLIT>>>(pos, Wp1, x, bp1, xn);
    // LN in place
    k_layernorm<<<Mm, 256>>>(xn, ln1g, ln1b);
    // attn = sigmoid(xn @ Ws - logS) -> out
    k_scores<<<Mm / 128, 256>>>(out_attn);
    // z = attn^T @ xn  (per batch)
    k_z<<<dim3(4, Bb), 256>>>(out_attn);
    // o = z @ Wv-blocks
    k_o<<<Bb * NCLS, 512>>>(Wkv);
    // head
    k_head<<<Bb * NCLS, 256>>>(Wproj, bproj, ln2g, ln2b, Wc1, bc1, Wc2, bc2, out);
}

// round 5
// speedup vs baseline: 4.6135x; 1.3222x over previous
#include <cuda_runtime.h>
#include <cuda_bf16.h>
#include <math.h>
#include <stdint.h>

// ---------------------------------------------------------------------------
// ConformalMIL forward.  B=32, S=2048, D=512, H=16, HD=32, NCLS=2, K=19
// out = [logits (32*2) | attn (32*16*2*2048)]  fp32
// GEMM1 single-pass tf32 mma.sync with cp.async pipeline; LN folded into
// scores/z algebraically (xn never materialized).
// ---------------------------------------------------------------------------

#define Bb 32
#define Ss 2048
#define Dd 512
#define Mm (Bb * Ss)          // 65536
#define Hh 16
#define HDd 32
#define NCLS 2
#define KS 19

// scratch (static device arrays; no cudaMalloc allowed)
__device__ float g_ksum[Dd * KS];
__device__ float g_pos[(size_t)Mm * Dd];             // conv out, tf32-rounded
__device__ float g_y[(size_t)Mm * Dd];               // y = pos@Wp1 + x + bp1
__device__ float g_wtf[Dd * Dd];                     // Wp1 tf32-rounded
__device__ float g_q[NCLS * Dd];
__device__ float g_ws[Dd * 32];                      // raw score weights
__device__ float g_ws2[Dd * 32];                     // ln1g-scaled
__device__ float g_t1[32], g_t2[32];
__device__ float2 g_part[4 * Mm];                    // per n-block row partials
__device__ float2 g_stats[Mm];                       // (mu, rsigma)
__device__ float g_z[Bb * 32 * Dd];
__device__ float g_o[Bb * NCLS * Dd];

// ---------------------------------------------------------------------------
// helpers
// ---------------------------------------------------------------------------
__device__ __forceinline__ uint32_t smem_u32(const void* p) {
    uint32_t a;
    asm("{ .reg .u64 t; cvta.to.shared.u64 t, %1; cvt.u32.u64 %0, t; }" : "=r"(a) : "l"(p));
    return a;
}
__device__ __forceinline__ float to_tf32(float f) {
    uint32_t u;
    asm("cvt.rna.tf32.f32 %0, %1;" : "=r"(u) : "f"(f));
    return __uint_as_float(u);
}
__device__ __forceinline__ void mma8(float* d, const uint32_t* a, const uint32_t* b) {
    asm volatile("mma.sync.aligned.m16n8k8.row.col.f32.tf32.tf32.f32 "
        "{%0,%1,%2,%3}, {%4,%5,%6,%7}, {%8,%9}, {%0,%1,%2,%3};"
        : "+f"(d[0]), "+f"(d[1]), "+f"(d[2]), "+f"(d[3])
        : "r"(a[0]), "r"(a[1]), "r"(a[2]), "r"(a[3]), "r"(b[0]), "r"(b[1]));
}

// ---------------------------------------------------------------------------
// 1. wavelet kernels
// ---------------------------------------------------------------------------
__global__ void k_wavelet(const float* __restrict__ w1, const float* __restrict__ w2,
                          const float* __restrict__ w3) {
    int d = blockIdx.x * blockDim.x + threadIdx.x;
    if (d >= Dd) return;
    const float C = 2.0f / (sqrtf(3.0f) * powf(3.14159265358979323846f, 0.25f));
    const float* ws[3] = {w1, w2, w3};
    float sc[3], sh[3], rs[3];
    #pragma unroll
    for (int w = 0; w < 3; w++) {
        sc[w] = ws[w][d];
        sh[w] = ws[w][Dd + d];
        rs[w] = rsqrtf(fabsf(sc[w]));
    }
    for (int t = 0; t < KS; t++) {
        float xt = (float)(t - 9);
        float acc = 0.f;
        #pragma unroll
        for (int w = 0; w < 3; w++) {
            float u = (xt - sh[w]) / sc[w];
            acc += C * (1.f - u * u) * expf(-0.5f * u * u) * rs[w];
        }
        g_ksum[d * KS + t] = acc;
    }
}

// ---------------------------------------------------------------------------
// 2. depthwise conv along S ('SAME'); output tf32-rounded (GEMM A operand)
// ---------------------------------------------------------------------------
__global__ void k_dwconv(const float* __restrict__ x) {
    const int b  = blockIdx.z;
    const int s0 = blockIdx.y * 32;
    const int d0 = blockIdx.x * 128;
    __shared__ float xs[50][128];
    __shared__ float ks[KS][128];
    const int tid = threadIdx.x;  // 256

    for (int i = tid; i < KS * 128; i += 256) {
        int t = i >> 7, d = i & 127;
        ks[t][d] = g_ksum[(d0 + d) * KS + t];
    }
    const float* xb = x + (size_t)b * Ss * Dd;
    for (int i = tid; i < 50 * 32; i += 256) {
        int r = i >> 5, c4 = (i & 31) * 4;
        int s = s0 - 9 + r;
        float4 v = make_float4(0.f, 0.f, 0.f, 0.f);
        if (s >= 0 && s < Ss) v = *(const float4*)(xb + (size_t)s * Dd + d0 + c4);
        *(float4*)&xs[r][c4] = v;
    }
    __syncthreads();

    const int d = tid & 127;
    const int sr0 = tid >> 7;
    #pragma unroll
    for (int j = 0; j < 16; j++) {
        int sr = sr0 + j * 2;
        float acc = 0.f;
        #pragma unroll
        for (int t = 0; t < KS; t++) acc = fmaf(xs[sr + t][d], ks[t][d], acc);
        g_pos[((size_t)b * Ss + s0 + sr) * Dd + d0 + d] = to_tf32(acc);
    }
}

// ---------------------------------------------------------------------------
// 2b. Wp1 -> tf32-rounded copy (GEMM B operand)
// ---------------------------------------------------------------------------
__global__ void k_wtf(const float* __restrict__ W) {
    int i = blockIdx.x * blockDim.x + threadIdx.x;
    if (i < Dd * Dd) g_wtf[i] = to_tf32(W[i]);
}

// ---------------------------------------------------------------------------
// 3. GEMM1 single-pass tf32:  y = pos @ Wp1 + x + bp1 ; per-row partial stats
//    CTA 128x128x32, 8 warps (2x4), warp 64x32, mma m16n8k8.
//    cp.async 3-stage pipeline; smem: A [128][32] (^ (r&7)<<2 on k),
//    B [32][128] (^ (k&3)<<3 on n).  Conflict-free LDS.32 fragment loads.
// ---------------------------------------------------------------------------
__device__ __forceinline__ void issue_stage(uint32_t base,
    const float* __restrict__ A, const float* __restrict__ Bw,
    int m0, int n0, int kt, int tid)
{
    #pragma unroll
    for (int i = 0; i < 4; i++) {
        int idx = tid + i * 256;
        int r = idx >> 3, c4 = (idx & 7) << 2;
        uint32_t dst = base + (uint32_t)(r * 32 + (c4 ^ ((r & 7) << 2))) * 4u;
        const float* src = A + (size_t)(m0 + r) * Dd + kt * 32 + c4;
        asm volatile("cp.async.ca.shared.global [%0], [%1], 16;" :: "r"(dst), "l"(src));
    }
    #pragma unroll
    for (int i = 0; i < 4; i++) {
        int idx = tid + i * 256;
        int kr = idx >> 5, c4 = (idx & 31) << 2;
        uint32_t dst = base + 16384u + (uint32_t)(kr * 128 + (c4 ^ ((kr & 3) << 3))) * 4u;
        const float* src = Bw + (size_t)(kt * 32 + kr) * Dd + n0 + c4;
        asm volatile("cp.async.ca.shared.global [%0], [%1], 16;" :: "r"(dst), "l"(src));
    }
}

__device__ __forceinline__ void compute_stage(const float* __restrict__ sA,
    const float* __restrict__ sB, int gid, int tig, int wmt, int wnt,
    float d[4][4][4])
{
    #pragma unroll
    for (int kt4 = 0; kt4 < 4; kt4++) {
        uint32_t a[4][4], b[4][2];
        const int k0 = kt4 * 8 + tig, k1 = k0 + 4;
        const int sw = gid << 2;
        #pragma unroll
        for (int mt = 0; mt < 4; mt++) {
            int r0 = (wmt + mt) * 16 + gid;
            a[mt][0] = __float_as_uint(sA[r0 * 32 + (k0 ^ sw)]);
            a[mt][1] = __float_as_uint(sA[(r0 + 8) * 32 + (k0 ^ sw)]);
            a[mt][2] = __float_as_uint(sA[r0 * 32 + (k1 ^ sw)]);
            a[mt][3] = __float_as_uint(sA[(r0 + 8) * 32 + (k1 ^ sw)]);
        }
        const int swb = (k0 & 3) << 3;
        #pragma unroll
        for (int nt = 0; nt < 4; nt++) {
            int n = (wnt + nt) * 8 + gid;
            b[nt][0] = __float_as_uint(sB[k0 * 128 + (n ^ swb)]);
            b[nt][1] = __float_as_uint(sB[k1 * 128 + (n ^ swb)]);
        }
        #pragma unroll
        for (int mt = 0; mt < 4; mt++)
            #pragma unroll
            for (int nt = 0; nt < 4; nt++) mma8(d[mt][nt], a[mt], b[nt]);
    }
}

__global__ void __launch_bounds__(256, 2) k_mma(
    const float* __restrict__ A, const float* __restrict__ Bw,
    const float* __restrict__ xres, const float* __restrict__ bias,
    float* __restrict__ outY)
{
    extern __shared__ float sm[];
    const int tid = threadIdx.x, warp = tid >> 5, lane = tid & 31;
    const int m0 = blockIdx.y * 128, n0 = blockIdx.x * 128;
    const int gid = lane >> 2, tig = lane & 3;
    const int wmt = (warp >> 2) * 4, wnt = (warp & 3) * 4;
    const uint32_t smb = smem_u32(sm);

    float d[4][4][4];
    #pragma unroll
    for (int i = 0; i < 4; i++)
        #pragma unroll
        for (int j = 0; j < 4; j++)
            #pragma unroll
            for (int r = 0; r < 4; r++) d[i][j][r] = 0.f;

    issue_stage(smb, A, Bw, m0, n0, 0, tid);
    asm volatile("cp.async.commit_group;" ::: "memory");
    issue_stage(smb + 32768u, A, Bw, m0, n0, 1, tid);
    asm volatile("cp.async.commit_group;" ::: "memory");

    int stc = 0, sti = 2;
    #pragma unroll 1
    for (int kt = 0; kt < 16; kt++) {
        if (kt < 14) asm volatile("cp.async.wait_group 1;" ::: "memory");
        else         asm volatile("cp.async.wait_group 0;" ::: "memory");
        __syncthreads();
        if (kt + 2 < 16) {
            issue_stage(smb + (uint32_t)sti * 32768u, A, Bw, m0, n0, kt + 2, tid);
            asm volatile("cp.async.commit_group;" ::: "memory");
            sti = (sti == 2) ? 0 : sti + 1;
        }
        compute_stage(sm + stc * 8192, sm + stc * 8192 + 4096, gid, tig, wmt, wnt, d);
        stc = (stc == 2) ? 0 : stc + 1;
    }

    // epilogue: v = d + x + bias -> y ; per-thread row sums -> smem -> g_part
    float rsum[8], rsq[8];
    #pragma unroll
    for (int i = 0; i < 8; i++) { rsum[i] = 0.f; rsq[i] = 0.f; }

    #pragma unroll
    for (int mt = 0; mt < 4; mt++) {
        #pragma unroll
        for (int nt = 0; nt < 4; nt++) {
            int row = m0 + (wmt + mt) * 16 + gid;
            int col = n0 + (wnt + nt) * 8 + tig * 2;
            float* D = d[mt][nt];
            float2 v0 = make_float2(D[0], D[1]);
            float2 v1 = make_float2(D[2], D[3]);
            const float* xr0 = xres + (size_t)row * Dd + col;
            const float* xr1 = xr0 + 8 * Dd;
            v0.x += xr0[0] + bias[col];     v0.y += xr0[1] + bias[col + 1];
            v1.x += xr1[0] + bias[col];     v1.y += xr1[1] + bias[col + 1];
            *(float2*)(outY + (size_t)row * Dd + col)       = v0;
            *(float2*)(outY + (size_t)(row + 8) * Dd + col) = v1;
            rsum[mt * 2]     += v0.x + v0.y;  rsq[mt * 2]     += v0.x * v0.x + v0.y * v0.y;
            rsum[mt * 2 + 1] += v1.x + v1.y;  rsq[mt * 2 + 1] += v1.x * v1.x + v1.y * v1.y;
        }
    }
    __syncthreads();                       // done with pipeline smem
    float2* ps = (float2*)sm;              // [128][17]
    const int slot = (warp & 3) * 4 + tig;
    #pragma unroll
    for (int mt = 0; mt < 4; mt++) {
        int r0 = (wmt + mt) * 16 + gid;
        ps[r0 * 17 + slot]       = make_float2(rsum[mt * 2], rsq[mt * 2]);
        ps[(r0 + 8) * 17 + slot] = make_float2(rsum[mt * 2 + 1], rsq[mt * 2 + 1]);
    }
    __syncthreads();
    if (tid < 128) {
        float s = 0.f, q = 0.f;
        #pragma unroll
        for (int i = 0; i < 16; i++) {
            float2 t = ps[tid * 17 + i];
            s += t.x; q += t.y;
        }
        g_part[(size_t)blockIdx.x * Mm + m0 + tid] = make_float2(s, q);
    }
}

// ---------------------------------------------------------------------------
// 3b. stats: mu, rsigma per row from 4 n-block partials
// ---------------------------------------------------------------------------
__global__ void k_stats() {
    int i = blockIdx.x * 256 + threadIdx.x;
    float s = 0.f, q = 0.f;
    #pragma unroll
    for (int nb = 0; nb < 4; nb++) {
        float2 p = g_part[(size_t)nb * Mm + i];
        s += p.x; q += p.y;
    }
    float mu = s * (1.f / Dd);
    float var = q * (1.f / Dd) - mu * mu;
    g_stats[i] = make_float2(mu, rsqrtf(var + 1e-5f));
}

// ---------------------------------------------------------------------------
// 4a. q = cls_token @ Wq  [2, 512]
// ---------------------------------------------------------------------------
__global__ void k_q(const float* __restrict__ cls, const float* __restrict__ Wq) {
    int idx = blockIdx.x * blockDim.x + threadIdx.x;
    int n = idx >> 9, j = idx & 511;
    float acc = 0.f;
    #pragma unroll 4
    for (int d = 0; d < Dd; d++) acc = fmaf(cls[n * Dd + d], Wq[(size_t)d * Dd + j], acc);
    g_q[n * Dd + j] = acc;
}

// ---------------------------------------------------------------------------
// 4b. ws[d][(h*2+n)] = scale * sum_hd Wkv[d][h*32+hd] * q[n][h*32+hd]
//     ws2 = ln1g[d] * ws
// ---------------------------------------------------------------------------
__global__ void k_ws(const float* __restrict__ Wkv, const float* __restrict__ ln1g) {
    int idx = blockIdx.x * blockDim.x + threadIdx.x;   // 16384
    int d = idx >> 5, c = idx & 31;
    int h = c >> 1, n = c & 1;
    const float scale = 0.17677669529663687f;   // 1/sqrt(32)
    float acc = 0.f;
    #pragma unroll
    for (int hd = 0; hd < HDd; hd++)
        acc = fmaf(Wkv[(size_t)d * (2 * Dd) + h * HDd + hd], g_q[n * Dd + h * HDd + hd], acc);
    acc *= scale;
    g_ws[d * 32 + c]  = acc;
    g_ws2[d * 32 + c] = ln1g[d] * acc;
}

// 4c. t1[c] = sum_d ws2 ; t2[c] = sum_d ln1b[d]*ws[d][c]
__global__ void k_wsfix(const float* __restrict__ ln1b) {
    const int c = blockIdx.x;      // 32 blocks, 128 threads
    const int t = threadIdx.x;
    float t1 = 0.f, t2 = 0.f;
    for (int d = t; d < Dd; d += 128) {
        t1 += g_ws2[d * 32 + c];
        t2 += ln1b[d] * g_ws[d * 32 + c];
    }
    #pragma unroll
    for (int o = 16; o; o >>= 1) {
        t1 += __shfl_xor_sync(~0u, t1, o);
        t2 += __shfl_xor_sync(~0u, t2, o);
    }
    __shared__ float s1[4], s2[4];
    if ((t & 31) == 0) { s1[t >> 5] = t1; s2[t >> 5] = t2; }
    __syncthreads();
    if (t == 0) {
        g_t1[c] = s1[0] + s1[1] + s1[2] + s1[3];
        g_t2[c] = s2[0] + s2[1] + s2[2] + s2[3];
    }
}

// ---------------------------------------------------------------------------
// 5. scores on raw y with folded LN:
//    score_c = rsig*(y . ws2_c) - rsig*mu*t1_c + t2_c ; attn = sigmoid(. - logS)
// ---------------------------------------------------------------------------
__global__ void __launch_bounds__(256) k_scores(float* __restrict__ out_attn) {
    __shared__ float xs[128][33];
    __shared__ float wss[32][32];
    __shared__ float t1s[32], t2s[32];
    const int tid = threadIdx.x;
    const int m0 = blockIdx.x * 128;
    const int rb = (tid >> 3) * 4;
    const int c0 = (tid & 7) * 4;
    const float logS = 7.6246189861593985f;

    if (tid < 32) { t1s[tid] = g_t1[tid]; t2s[tid] = g_t2[tid]; }

    float acc[4][4];
    #pragma unroll
    for (int i = 0; i < 4; i++)
        #pragma unroll
        for (int j = 0; j < 4; j++) acc[i][j] = 0.f;

    for (int k0 = 0; k0 < Dd; k0 += 32) {
        #pragma unroll
        for (int l = 0; l < 4; l++) {
            int idx = tid + l * 256;
            int r = idx >> 3, k4 = (idx & 7) * 4;
            float4 v = *(const float4*)(g_y + (size_t)(m0 + r) * Dd + k0 + k4);
            xs[r][k4] = v.x; xs[r][k4 + 1] = v.y; xs[r][k4 + 2] = v.z; xs[r][k4 + 3] = v.w;
        }
        {
            int kk = tid >> 3, c4 = (tid & 7) * 4;
            *(float4*)&wss[kk][c4] = *(const float4*)(g_ws2 + (size_t)(k0 + kk) * 32 + c4);
        }
        __syncthreads();
        #pragma unroll 4
        for (int kk = 0; kk < 32; kk++) {
            float w[4], a[4];
            #pragma unroll
            for (int j = 0; j < 4; j++) w[j] = wss[kk][c0 + j];
            #pragma unroll
            for (int i = 0; i < 4; i++) a[i] = xs[rb + i][kk];
            #pragma unroll
            for (int i = 0; i < 4; i++)
                #pragma unroll
                for (int j = 0; j < 4; j++) acc[i][j] = fmaf(a[i], w[j], acc[i][j]);
        }
        __syncthreads();
    }
    #pragma unroll
    for (int i = 0; i < 4; i++) {
        int m = m0 + rb + i;
        int b = m >> 11, s = m & 2047;
        float2 st = g_stats[m];
        #pragma unroll
        for (int j = 0; j < 4; j++) {
            int c = c0 + j;
            float score = st.y * (acc[i][j] - st.x * t1s[c]) + t2s[c];
            float a = 1.f / (1.f + expf(logS - score));
            out_attn[(size_t)b * (Hh * NCLS * Ss) + (size_t)c * Ss + s] = a;
        }
    }
}

// ---------------------------------------------------------------------------
// 6. z from raw y:  z[c][d] = g_d*(sum_s a'_cs y_sd - Q_c) + b_d*R_c
//    a' = attn*rsig ; Q_c = sum a'*mu ; R_c = sum attn
// ---------------------------------------------------------------------------
__global__ void __launch_bounds__(256) k_z(const float* __restrict__ attn,
                                           const float* __restrict__ ln1g,
                                           const float* __restrict__ ln1b) {
    __shared__ float at[32][65];
    __shared__ float xs[64][128];
    __shared__ float sQ[32], sR[32];
    const int tid = threadIdx.x;
    const int b = blockIdx.y;
    const int n0 = blockIdx.x * 128;
    const int rb = (tid >> 5) * 4;
    const int cb = (tid & 31) * 4;

    if (tid < 32) { sQ[tid] = 0.f; sR[tid] = 0.f; }

    float acc[4][4];
    #pragma unroll
    for (int i = 0; i < 4; i++)
        #pragma unroll
        for (int j = 0; j < 4; j++) acc[i][j] = 0.f;
    float qacc[8], racc[8];
    #pragma unroll
    for (int l = 0; l < 8; l++) { qacc[l] = 0.f; racc[l] = 0.f; }

    const float* ab = attn + (size_t)b * (Hh * NCLS * Ss);
    const float* yb = g_y + (size_t)b * Ss * Dd;

    for (int s0 = 0; s0 < Ss; s0 += 64) {
        #pragma unroll
        for (int l = 0; l < 8; l++) {
            int idx = tid + l * 256;
            int hn = idx >> 6, so = idx & 63;
            float raw = ab[(size_t)hn * Ss + s0 + so];
            float2 st = g_stats[b * Ss + s0 + so];
            at[hn][so] = raw * st.y;
            racc[l] += raw;
            qacc[l] += raw * st.y * st.x;
        }
        #pragma unroll
        for (int l = 0; l < 8; l++) {
            int idx = tid + l * 256;
            int ss = idx >> 5, d4 = (idx & 31) * 4;
            *(float4*)&xs[ss][d4] = *(const float4*)(yb + (size_t)(s0 + ss) * Dd + n0 + d4);
        }
        __syncthreads();
        #pragma unroll 4
        for (int ss = 0; ss < 64; ss++) {
            float4 xv = *(float4*)&xs[ss][cb];
            float a[4];
            #pragma unroll
            for (int i = 0; i < 4; i++) a[i] = at[rb + i][ss];
            #pragma unroll
            for (int i = 0; i < 4; i++) {
                acc[i][0] = fmaf(a[i], xv.x, acc[i][0]);
                acc[i][1] = fmaf(a[i], xv.y, acc[i][1]);
                acc[i][2] = fmaf(a[i], xv.z, acc[i][2]);
                acc[i][3] = fmaf(a[i], xv.w, acc[i][3]);
            }
        }
        __syncthreads();
    }
    #pragma unroll
    for (int l = 0; l < 8; l++) {
        int hn = (tid >> 6) + l * 4;
        atomicAdd(&sQ[hn], qacc[l]);
        atomicAdd(&sR[hn], racc[l]);
    }
    __syncthreads();
    const float4 gg = *(const float4*)(ln1g + n0 + cb);
    const float4 bb = *(const float4*)(ln1b + n0 + cb);
    #pragma unroll
    for (int i = 0; i < 4; i++) {
        int c = rb + i;
        float Q = sQ[c], R = sR[c];
        float4 v;
        v.x = gg.x * (acc[i][0] - Q) + bb.x * R;
        v.y = gg.y * (acc[i][1] - Q) + bb.y * R;
        v.z = gg.z * (acc[i][2] - Q) + bb.z * R;
        v.w = gg.w * (acc[i][3] - Q) + bb.w * R;
        *(float4*)(g_z + ((size_t)b * 32 + c) * Dd + n0 + cb) = v;
    }
}

// ---------------------------------------------------------------------------
// 7. o[b][n][h*32+d'] = sum_d z[b][(h*2+n)][d] * Wkv[d][512 + h*32+d']
// ---------------------------------------------------------------------------
__global__ void __launch_bounds__(512) k_o(const float* __restrict__ Wkv) {
    __shared__ float zr[16][Dd];
    const int bn = blockIdx.x;
    const int b = bn >> 1, n = bn & 1;
    const int j = threadIdx.x;           // 512
    for (int i = j; i < 16 * Dd; i += 512) {
        int h = i >> 9, d = i & 511;
        zr[h][d] = g_z[((size_t)b * 32 + h * 2 + n) * Dd + d];
    }
    __syncthreads();
    const int h = j >> 5;
    float acc = 0.f;
    #pragma unroll 4
    for (int d = 0; d < Dd; d++)
        acc = fmaf(zr[h][d], Wkv[(size_t)d * (2 * Dd) + Dd + j], acc);
    g_o[(size_t)bn * Dd + j] = acc;
}

// ---------------------------------------------------------------------------
// 8. head (fp32)
// ---------------------------------------------------------------------------
__global__ void k_head(const float* __restrict__ Wproj, const float* __restrict__ bproj,
                       const float* __restrict__ ln2g, const float* __restrict__ ln2b,
                       const float* __restrict__ Wc1, const float* __restrict__ bc1,
                       const float* __restrict__ Wc2, const float* __restrict__ bc2,
                       float* __restrict__ logits) {
    const int r = blockIdx.x;
    const int tid = threadIdx.x;  // 256
    __shared__ float orow[Dd];
    __shared__ float prow[Dd];
    __shared__ float rs[8], rq[8];
    __shared__ float s_m, s_r;
    orow[tid]       = g_o[r * Dd + tid];
    orow[tid + 256] = g_o[r * Dd + tid + 256];
    __syncthreads();

    float pv[2];
    #pragma unroll
    for (int l = 0; l < 2; l++) {
        int j = tid + l * 256;
        float acc = bproj[j];
        #pragma unroll 4
        for (int d = 0; d < Dd; d++) acc = fmaf(orow[d], Wproj[(size_t)d * Dd + j], acc);
        pv[l] = acc;
    }
    float sum = pv[0] + pv[1];
    float sq  = pv[0] * pv[0] + pv[1] * pv[1];
    #pragma unroll
    for (int o = 16; o; o >>= 1) {
        sum += __shfl_xor_sync(~0u, sum, o);
        sq  += __shfl_xor_sync(~0u, sq, o);
    }
    if ((tid & 31) == 0) { rs[tid >> 5] = sum; rq[tid >> 5] = sq; }
    __syncthreads();
    if (tid == 0) {
        float s = 0.f, q = 0.f;
        #pragma unroll
        for (int i = 0; i < 8; i++) { s += rs[i]; q += rq[i]; }
        float m = s / Dd;
        float v = q / Dd - m * m;
        s_m = m; s_r = rsqrtf(v + 1e-5f);
    }
    __syncthreads();
    #pragma unroll
    for (int l = 0; l < 2; l++) {
        int j = tid + l * 256;
        prow[j] = (pv[l] - s_m) * s_r * ln2g[j] + ln2b[j];
    }
    __syncthreads();

    float part = 0.f;
    #pragma unroll
    for (int l = 0; l < 2; l++) {
        int j = tid + l * 256;
        float acc = bc1[j];
        #pragma unroll 4
        for (int d = 0; d < Dd; d++) acc = fmaf(prow[d], Wc1[(size_t)d * Dd + j], acc);
        acc = fmaxf(acc, 0.f);
        part = fmaf(acc, Wc2[j], part);
    }
    #pragma unroll
    for (int o = 16; o; o >>= 1) part += __shfl_xor_sync(~0u, part, o);
    if ((tid & 31) == 0) rs[tid >> 5] = part;
    __syncthreads();
    if (tid == 0) {
        float s = 0.f;
        #pragma unroll
        for (int i = 0; i < 8; i++) s += rs[i];
        logits[r] = s + bc2[0];
    }
}

// ---------------------------------------------------------------------------
extern "C" void kernel_launch(void* const* d_in, const int* in_sizes, int n_in,
                              void* d_out, int out_size) {
    const float* x      = (const float*)d_in[0];
    const float* wave1  = (const float*)d_in[1];
    const float* wave2  = (const float*)d_in[2];
    const float* wave3  = (const float*)d_in[3];
    const float* Wp1    = (const float*)d_in[4];
    const float* bp1    = (const float*)d_in[5];
    const float* cls    = (const float*)d_in[6];
    const float* ln1g   = (const float*)d_in[7];
    const float* ln1b   = (const float*)d_in[8];
    const float* Wq     = (const float*)d_in[9];
    const float* Wkv    = (const float*)d_in[10];
    const float* Wproj  = (const float*)d_in[11];
    const float* bproj  = (const float*)d_in[12];
    const float* ln2g   = (const float*)d_in[13];
    const float* ln2b   = (const float*)d_in[14];
    const float* Wc1    = (const float*)d_in[15];
    const float* bc1    = (const float*)d_in[16];
    const float* Wc2    = (const float*)d_in[17];
    const float* bc2    = (const float*)d_in[18];

    float* out = (float*)d_out;           // [0,64) logits, [64, ...) attn
    float* out_attn = out + Bb * NCLS;

    float* pos;  cudaGetSymbolAddress((void**)&pos,  g_pos);
    float* y;    cudaGetSymbolAddress((void**)&y,    g_y);
    float* wtf;  cudaGetSymbolAddress((void**)&wtf,  g_wtf);

    const int SMEMSZ = 3 * 32768;   // 96 KB
    cudaFuncSetAttribute(k_mma, cudaFuncAttributeMaxDynamicSharedMemorySize, SMEMSZ);

    // wavelet + conv (tf32-rounded pos) + weight prep
    k_wavelet<<<1, 512>>>(wave1, wave2, wave3);
    k_dwconv<<<dim3(Dd / 128, Ss / 32, Bb), 256>>>(x);
    k_wtf<<<(Dd * Dd) / 1024, 1024>>>(Wp1);
    // q / ws / fixups (independent)
    k_q<<<4, 256>>>(cls, Wq);
    k_ws<<<64, 256>>>(Wkv, ln1g);
    k_wsfix<<<32, 128>>>(ln1b);
    // GEMM1 single-pass tf32: y = pos @ Wp1 + x + bp1 (+ row stat partials)
    k_mma<<<dim3(4, Mm / 128), 256, SMEMSZ>>>(pos, wtf, x, bp1, y);
    k_stats<<<Mm / 256, 256>>>();
    // attn = sigmoid(folded-LN scores) -> out
    k_scores<<<Mm / 128, 256>>>(out_attn);
    // z = g*(a'^T y - Q) + b*R   (per batch)
    k_z<<<dim3(4, Bb), 256>>>(out_attn, ln1g, ln1b);
    // o, head
    k_o<<<Bb * NCLS, 512>>>(Wkv);
    k_head<<<Bb * NCLS, 256>>>(Wproj, bproj, ln2g, ln2b, Wc1, bc1, Wc2, bc2, out);
}